// round 1
// baseline (speedup 1.0000x reference)
#include <cuda_runtime.h>
#include <cuda_bf16.h>

#define BATCH     8192
#define IN_CAP_SZ 5
#define IN_CAP_N  1152
#define OUT_CAP_N 55
#define F4_PER_K  288    // 1152/4 float4 per (b,i) row
#define F4_PER_B  1440   // 5*288 float4 per batch element

__global__ __launch_bounds__(256) void digitcaps_kernel(
    const float4* __restrict__ u4,   // (B, 5, 1152) as float4
    const float4* __restrict__ w4,   // (1152,) as float4
    const float*  __restrict__ bvec, // (55,)
    float*        __restrict__ out)  // (B, 55)
{
    __shared__ float4 ws[F4_PER_K];
    const int tid = threadIdx.x;
    for (int idx = tid; idx < F4_PER_K; idx += 256)
        ws[idx] = w4[idx];
    __syncthreads();

    const int lane = tid & 31;
    const int warp = tid >> 5;
    const int b    = blockIdx.x * 8 + warp;   // grid=1024, 8 warps/block -> exactly 8192

    // ---- Phase 1: u_hat[i] = sum_k u[b,i,k] * W[k], fully coalesced float4 ----
    const float4* up = u4 + (size_t)b * F4_PER_B;

    float uh[5];
    #pragma unroll
    for (int i = 0; i < 5; i++) {
        float a = 0.f;
        #pragma unroll
        for (int j = 0; j < 9; j++) {           // 9*32 = 288 float4 = 1152 floats
            float4 x = up[i * F4_PER_K + j * 32 + lane];
            float4 w = ws[j * 32 + lane];
            a = fmaf(x.x, w.x, a);
            a = fmaf(x.y, w.y, a);
            a = fmaf(x.z, w.z, a);
            a = fmaf(x.w, w.w, a);
        }
        // warp butterfly reduce -> all lanes hold uh[i]
        #pragma unroll
        for (int off = 16; off > 0; off >>= 1)
            a += __shfl_xor_sync(0xffffffffu, a, off);
        uh[i] = a;
    }

    // ---- Phase 2: 2 routing iterations, lanes own out-capsules lane and lane+32 ----
    const int  o0   = lane;
    const int  o1   = lane + 32;
    const bool has1 = (o1 < OUT_CAP_N);

    float bij0[5], bij1[5];
    {
        const float b0 = bvec[o0];
        const float b1 = has1 ? bvec[o1] : 0.f;
        #pragma unroll
        for (int i = 0; i < 5; i++) { bij0[i] = b0; bij1[i] = b1; }
    }

    float v0 = 0.f, v1 = 0.f;
    #pragma unroll
    for (int it = 0; it < 2; it++) {
        float s0 = 0.f, s1 = 0.f;
        #pragma unroll
        for (int i = 0; i < 5; i++) {
            // softmax over the 55 out-capsules for this input capsule i
            float m = bij0[i];
            if (has1) m = fmaxf(m, bij1[i]);
            #pragma unroll
            for (int off = 16; off > 0; off >>= 1)
                m = fmaxf(m, __shfl_xor_sync(0xffffffffu, m, off));

            const float e0 = expf(bij0[i] - m);
            const float e1 = has1 ? expf(bij1[i] - m) : 0.f;
            float d = e0 + e1;
            #pragma unroll
            for (int off = 16; off > 0; off >>= 1)
                d += __shfl_xor_sync(0xffffffffu, d, off);

            const float cu = uh[i] / d;   // fold c = e/d with u_hat multiply
            s0 = fmaf(e0, cu, s0);
            s1 = fmaf(e1, cu, s1);
        }
        // squash for OUT_CAP_SZ=1:  v = |s| / (1 + s^2) * s
        v0 = fabsf(s0) / (1.f + s0 * s0) * s0;
        v1 = fabsf(s1) / (1.f + s1 * s1) * s1;

        if (it == 0) {
            #pragma unroll
            for (int i = 0; i < 5; i++) {
                bij0[i] = fmaf(v0, uh[i], bij0[i]);
                bij1[i] = fmaf(v1, uh[i], bij1[i]);
            }
        }
    }

    out[(size_t)b * OUT_CAP_N + o0] = v0;
    if (has1) out[(size_t)b * OUT_CAP_N + o1] = v1;
}

extern "C" void kernel_launch(void* const* d_in, const int* in_sizes, int n_in,
                              void* d_out, int out_size) {
    const float4* u4   = (const float4*)d_in[0];  // (8192,5,128,3,3) f32, contiguous
    const float4* w4   = (const float4*)d_in[1];  // (1,1152,1) f32
    const float*  bvec = (const float*) d_in[2];  // (55,1) f32
    float*        out  = (float*)d_out;           // (8192,55,1) f32

    digitcaps_kernel<<<BATCH / 8, 256>>>(u4, w4, bvec, out);
}

// round 2
// speedup vs baseline: 1.2350x; 1.2350x over previous
#include <cuda_runtime.h>
#include <cuda_bf16.h>

#define BATCH     8192
#define IN_CAP_SZ 5
#define IN_CAP_N  1152
#define OUT_CAP_N 55
#define F4_PER_K  288    // 1152/4 float4 per (b,i) row
#define F4_PER_B  1440   // 5*288 float4 per batch element

__global__ __launch_bounds__(128) void digitcaps_kernel(
    const float4* __restrict__ u4,   // (B, 5, 1152) as float4
    const float4* __restrict__ w4,   // (1152,) as float4
    const float*  __restrict__ bvec, // (55,)
    float*        __restrict__ out)  // (B, 55)
{
    __shared__ float4 ws[F4_PER_K];
    const int tid = threadIdx.x;
    for (int idx = tid; idx < F4_PER_K; idx += 128)
        ws[idx] = w4[idx];
    __syncthreads();

    const int lane = tid & 31;
    const int warp = tid >> 5;
    const int b    = blockIdx.x * 4 + warp;   // grid=2048, 4 warps/block -> 8192

    // ---- Phase 1: uh[i] = sum_k u[b,i,k]*W[k]. j-outer => 5 independent
    //      load+FMA chains per step (deep MLP), reductions deferred+interleaved.
    const float4* up = u4 + (size_t)b * F4_PER_B + lane;

    float acc[5] = {0.f, 0.f, 0.f, 0.f, 0.f};
    #pragma unroll
    for (int j = 0; j < 9; j++) {
        float4 x0 = up[0 * F4_PER_K + j * 32];
        float4 x1 = up[1 * F4_PER_K + j * 32];
        float4 x2 = up[2 * F4_PER_K + j * 32];
        float4 x3 = up[3 * F4_PER_K + j * 32];
        float4 x4 = up[4 * F4_PER_K + j * 32];
        float4 w  = ws[j * 32 + lane];
        acc[0] = fmaf(x0.x, w.x, fmaf(x0.y, w.y, fmaf(x0.z, w.z, fmaf(x0.w, w.w, acc[0]))));
        acc[1] = fmaf(x1.x, w.x, fmaf(x1.y, w.y, fmaf(x1.z, w.z, fmaf(x1.w, w.w, acc[1]))));
        acc[2] = fmaf(x2.x, w.x, fmaf(x2.y, w.y, fmaf(x2.z, w.z, fmaf(x2.w, w.w, acc[2]))));
        acc[3] = fmaf(x3.x, w.x, fmaf(x3.y, w.y, fmaf(x3.z, w.z, fmaf(x3.w, w.w, acc[3]))));
        acc[4] = fmaf(x4.x, w.x, fmaf(x4.y, w.y, fmaf(x4.z, w.z, fmaf(x4.w, w.w, acc[4]))));
    }

    // 5 interleaved butterfly reductions (independent SHFL chains pipeline)
    #pragma unroll
    for (int off = 16; off > 0; off >>= 1) {
        #pragma unroll
        for (int i = 0; i < 5; i++)
            acc[i] += __shfl_xor_sync(0xffffffffu, acc[i], off);
    }
    // all lanes now hold uh[i] = acc[i]

    // ---- Phase 2: routing. Lane owns out-capsules o0=lane, o1=lane+32. ----
    const int  o0   = lane;
    const int  o1   = lane + 32;
    const bool has1 = (o1 < OUT_CAP_N);

    const float base0 = bvec[o0];
    const float base1 = has1 ? bvec[o1] : 0.f;

    // Iteration 0: b_ij is i-independent (broadcast of (55,1)) => one softmax,
    // and s_o = c_o * sum_i uh_i.
    float m = has1 ? fmaxf(base0, base1) : base0;
    #pragma unroll
    for (int off = 16; off > 0; off >>= 1)
        m = fmaxf(m, __shfl_xor_sync(0xffffffffu, m, off));

    float e0 = __expf(base0 - m);
    float e1 = has1 ? __expf(base1 - m) : 0.f;
    float d  = e0 + e1;
    #pragma unroll
    for (int off = 16; off > 0; off >>= 1)
        d += __shfl_xor_sync(0xffffffffu, d, off);

    const float sumUh = acc[0] + acc[1] + acc[2] + acc[3] + acc[4];
    const float r0    = __fdividef(sumUh, d);
    float s0 = e0 * r0;
    float s1 = e1 * r0;
    // squash (OUT_CAP_SZ=1): v = |s|/(1+s^2) * s
    float v0 = __fdividef(fabsf(s0) * s0, 1.f + s0 * s0);
    float v1 = __fdividef(fabsf(s1) * s1, 1.f + s1 * s1);

    // Iteration 1 (final): b_ij(o,i) = base_o + v_o*uh_i. 5 interleaved softmaxes.
    float mi[5];
    #pragma unroll
    for (int i = 0; i < 5; i++) {
        float t0 = fmaf(v0, acc[i], base0);
        mi[i] = t0;
        if (has1) mi[i] = fmaxf(mi[i], fmaf(v1, acc[i], base1));
    }
    #pragma unroll
    for (int off = 16; off > 0; off >>= 1) {
        #pragma unroll
        for (int i = 0; i < 5; i++)
            mi[i] = fmaxf(mi[i], __shfl_xor_sync(0xffffffffu, mi[i], off));
    }

    float e0i[5], e1i[5], di[5];
    #pragma unroll
    for (int i = 0; i < 5; i++) {
        e0i[i] = __expf(fmaf(v0, acc[i], base0) - mi[i]);
        e1i[i] = has1 ? __expf(fmaf(v1, acc[i], base1) - mi[i]) : 0.f;
        di[i]  = e0i[i] + e1i[i];
    }
    #pragma unroll
    for (int off = 16; off > 0; off >>= 1) {
        #pragma unroll
        for (int i = 0; i < 5; i++)
            di[i] += __shfl_xor_sync(0xffffffffu, di[i], off);
    }

    float t0 = 0.f, t1 = 0.f;
    #pragma unroll
    for (int i = 0; i < 5; i++) {
        const float r = __fdividef(acc[i], di[i]);
        t0 = fmaf(e0i[i], r, t0);
        t1 = fmaf(e1i[i], r, t1);
    }
    const float w0 = __fdividef(fabsf(t0) * t0, 1.f + t0 * t0);
    const float w1 = __fdividef(fabsf(t1) * t1, 1.f + t1 * t1);

    out[(size_t)b * OUT_CAP_N + o0] = w0;
    if (has1) out[(size_t)b * OUT_CAP_N + o1] = w1;
}

extern "C" void kernel_launch(void* const* d_in, const int* in_sizes, int n_in,
                              void* d_out, int out_size) {
    const float4* u4   = (const float4*)d_in[0];  // (8192,5,128,3,3) f32
    const float4* w4   = (const float4*)d_in[1];  // (1,1152,1) f32
    const float*  bvec = (const float*) d_in[2];  // (55,1) f32
    float*        out  = (float*)d_out;           // (8192,55,1) f32

    digitcaps_kernel<<<BATCH / 4, 128>>>(u4, w4, bvec, out);
}